// round 14
// baseline (speedup 1.0000x reference)
#include <cuda_runtime.h>
#include <cuda_fp16.h>
#include <math.h>

#define NMAX 100000
#define EMAX 1600000
#define HID 64
#define NGRAPHS 64
#define JKDIM 192
#define SCAN_BLK 1024
#define MAX_SCAN_BLOCKS 128

// ---------------- scratch (device globals: no allocation allowed) ----------
__device__ int    g_deg[NMAX];
__device__ int    g_rowptr[NMAX + 1];
__device__ int    g_cursor[NMAX];
__device__ int    g_scanloc[NMAX];
__device__ int    g_blocksum[MAX_SCAN_BLOCKS];
__device__ int    g_blockoff[MAX_SCAN_BLOCKS];
__device__ int    g_csr_src[EMAX];
__device__ float  g_dinv[NMAX];
__device__ __half g_ysh [(size_t)NMAX * HID];  // ping
__device__ __half g_ysh2[(size_t)NMAX * HID];  // pong
__device__ float  g_pooled[NGRAPHS * JKDIM];
__device__ float  g_cnt[NGRAPHS];

__device__ __forceinline__ unsigned int h2bits(__half2 h) {
    return *(unsigned int*)&h;
}
__device__ __forceinline__ unsigned int smem_u32(const void* p) {
    unsigned int a;
    asm("{ .reg .u64 t; cvta.to.shared.u64 t, %1; cvt.u32.u64 %0, t; }"
        : "=r"(a) : "l"(p));
    return a;
}

// ---------------- init ------------------------------------------------------
__global__ void zero_kernel(int N) {
    int i = blockIdx.x * blockDim.x + threadIdx.x;
    if (i < N) g_deg[i] = 0;
    if (i < NGRAPHS * JKDIM) g_pooled[i] = 0.f;
    if (i < NGRAPHS) g_cnt[i] = 0.f;
}

__global__ void degree_kernel(const int* __restrict__ ei, int E) {
    int e = blockIdx.x * blockDim.x + threadIdx.x;
    if (e < E) atomicAdd(&g_deg[ei[E + e]], 1);
}

// ---------------- scan (also computes dinv) ----------------------------------
__global__ __launch_bounds__(SCAN_BLK) void block_scan_kernel(int N) {
    __shared__ int bs[SCAN_BLK];
    int t = threadIdx.x;
    int i = blockIdx.x * SCAN_BLK + t;
    int v = (i < N) ? g_deg[i] : 0;
    if (i < N) g_dinv[i] = rsqrtf((float)(v + 1));  // +1 self loop
    bs[t] = v;
    __syncthreads();
#pragma unroll
    for (int off = 1; off < SCAN_BLK; off <<= 1) {
        int u = (t >= off) ? bs[t - off] : 0;
        __syncthreads();
        bs[t] += u;
        __syncthreads();
    }
    if (i < N) g_scanloc[i] = bs[t] - v;
    if (t == SCAN_BLK - 1) g_blocksum[blockIdx.x] = bs[t];
}

__global__ void scan_blocksums_kernel(int nb) {
    __shared__ int bs[MAX_SCAN_BLOCKS];
    int t = threadIdx.x;
    int v = (t < nb) ? g_blocksum[t] : 0;
    bs[t] = v;
    __syncthreads();
#pragma unroll
    for (int off = 1; off < MAX_SCAN_BLOCKS; off <<= 1) {
        int u = (t >= off) ? bs[t - off] : 0;
        __syncthreads();
        bs[t] += u;
        __syncthreads();
    }
    if (t < nb) g_blockoff[t] = bs[t] - v;
}

__global__ void apply_offsets_kernel(int N, int E) {
    int i = blockIdx.x * blockDim.x + threadIdx.x;
    if (i < N) {
        int r = g_scanloc[i] + g_blockoff[i / SCAN_BLK];
        g_rowptr[i] = r;
        g_cursor[i] = r;
    }
    if (i == 0) g_rowptr[N] = E;
}

__global__ void fill_kernel(const int* __restrict__ ei, int E) {
    int e = blockIdx.x * blockDim.x + threadIdx.x;
    if (e < E) {
        int d = ei[E + e];
        int pos = atomicAdd(&g_cursor[d], 1);
        g_csr_src[pos] = ei[e];
    }
}

// -------- HMMA GEMM (layer 1 only): ysh = fp16((x @ W1) * dinv[row]) --------
template <int KTOT>
__global__ __launch_bounds__(256) void gemm_hmma(const float* __restrict__ Af,
                                                 const float* __restrict__ W,
                                                 int N) {
    __shared__ __half As[128][40];
    __shared__ __half Bs[32][72];

    int tid = threadIdx.x;
    int warp = tid >> 5;
    int lane = tid & 31;
    int rowBase = blockIdx.x * 128;
    int wrow = warp * 16;

    float acc[8][4];
#pragma unroll
    for (int i = 0; i < 8; i++)
#pragma unroll
        for (int j = 0; j < 4; j++) acc[i][j] = 0.f;

    for (int kc = 0; kc < KTOT; kc += 32) {
        {
            int ar = tid >> 1;
            int ak = (tid & 1) * 16;
            int grow = rowBase + ar;
            uint4 u0 = make_uint4(0, 0, 0, 0);
            uint4 u1 = make_uint4(0, 0, 0, 0);
            if (grow < N) {
                const float4* p = (const float4*)(Af + (size_t)grow * KTOT + kc + ak);
                float4 f0 = p[0], f1 = p[1], f2 = p[2], f3 = p[3];
                u0.x = h2bits(__floats2half2_rn(f0.x, f0.y));
                u0.y = h2bits(__floats2half2_rn(f0.z, f0.w));
                u0.z = h2bits(__floats2half2_rn(f1.x, f1.y));
                u0.w = h2bits(__floats2half2_rn(f1.z, f1.w));
                u1.x = h2bits(__floats2half2_rn(f2.x, f2.y));
                u1.y = h2bits(__floats2half2_rn(f2.z, f2.w));
                u1.z = h2bits(__floats2half2_rn(f3.x, f3.y));
                u1.w = h2bits(__floats2half2_rn(f3.z, f3.w));
            }
            *(uint4*)&As[ar][ak] = u0;
            *(uint4*)&As[ar][ak + 8] = u1;
        }
        {
            int br = tid >> 3;
            int bc = (tid & 7) * 8;
            const float4* p = (const float4*)(W + (size_t)(kc + br) * 64 + bc);
            float4 w0 = p[0], w1 = p[1];
            uint4 u;
            u.x = h2bits(__floats2half2_rn(w0.x, w0.y));
            u.y = h2bits(__floats2half2_rn(w0.z, w0.w));
            u.z = h2bits(__floats2half2_rn(w1.x, w1.y));
            u.w = h2bits(__floats2half2_rn(w1.z, w1.w));
            *(uint4*)&Bs[br][bc] = u;
        }
        __syncthreads();

#pragma unroll
        for (int c = 0; c < 2; c++) {
            unsigned int a0, a1, a2, a3;
            unsigned int aaddr =
                smem_u32(&As[wrow + (lane & 15)][c * 16 + (lane >> 4) * 8]);
            asm volatile(
                "ldmatrix.sync.aligned.m8n8.x4.shared.b16 {%0,%1,%2,%3}, [%4];"
                : "=r"(a0), "=r"(a1), "=r"(a2), "=r"(a3) : "r"(aaddr));

#pragma unroll
            for (int nb = 0; nb < 8; nb += 2) {
                unsigned int b0, b1, b2, b3;
                unsigned int baddr =
                    smem_u32(&Bs[c * 16 + (lane & 15)][nb * 8 + (lane >> 4) * 8]);
                asm volatile(
                    "ldmatrix.sync.aligned.m8n8.x4.trans.shared.b16 {%0,%1,%2,%3}, [%4];"
                    : "=r"(b0), "=r"(b1), "=r"(b2), "=r"(b3) : "r"(baddr));
                asm volatile(
                    "mma.sync.aligned.m16n8k16.row.col.f32.f16.f16.f32 "
                    "{%0,%1,%2,%3}, {%4,%5,%6,%7}, {%8,%9}, {%0,%1,%2,%3};"
                    : "+f"(acc[nb][0]), "+f"(acc[nb][1]),
                      "+f"(acc[nb][2]), "+f"(acc[nb][3])
                    : "r"(a0), "r"(a1), "r"(a2), "r"(a3), "r"(b0), "r"(b1));
                asm volatile(
                    "mma.sync.aligned.m16n8k16.row.col.f32.f16.f16.f32 "
                    "{%0,%1,%2,%3}, {%4,%5,%6,%7}, {%8,%9}, {%0,%1,%2,%3};"
                    : "+f"(acc[nb + 1][0]), "+f"(acc[nb + 1][1]),
                      "+f"(acc[nb + 1][2]), "+f"(acc[nb + 1][3])
                    : "r"(a0), "r"(a1), "r"(a2), "r"(a3), "r"(b2), "r"(b3));
            }
        }
        __syncthreads();
    }

    int gID = lane >> 2;
    int tID = lane & 3;
    int r0 = rowBase + wrow + gID;
    int r1 = r0 + 8;
    float dv0 = (r0 < N) ? g_dinv[r0] : 0.f;
    float dv1 = (r1 < N) ? g_dinv[r1] : 0.f;
#pragma unroll
    for (int nb = 0; nb < 8; nb++) {
        int col = nb * 8 + tID * 2;
        if (r0 < N) {
            __half2 p = __floats2half2_rn(acc[nb][0] * dv0, acc[nb][1] * dv0);
            *(__half2*)(g_ysh + (size_t)r0 * HID + col) = p;
        }
        if (r1 < N) {
            __half2 p = __floats2half2_rn(acc[nb][2] * dv1, acc[nb][3] * dv1);
            *(__half2*)(g_ysh + (size_t)r1 * HID + col) = p;
        }
    }
}

// ---- fused aggregate + pool + NEXT-layer GEMM -------------------------------
// h[n] = relu(dinv[n]*(ysin[n] + sum ysin[src]) + b)
// if Wnext: ysout[n] = fp16(dinv[n] * (h[n] @ Wnext))
__device__ __forceinline__ void add_h4(float* acc, uint2 v) {
    __half2 h0 = *(__half2*)&v.x;
    __half2 h1 = *(__half2*)&v.y;
    float2 f0 = __half22float2(h0);
    float2 f1 = __half22float2(h1);
    acc[0] += f0.x; acc[1] += f0.y;
    acc[2] += f1.x; acc[3] += f1.y;
}

__global__ __launch_bounds__(256) void agg_gemm_kernel(
    const float* __restrict__ bias, const int* __restrict__ batch,
    const float* __restrict__ Wnext,   // null -> no fused gemm (layer 4)
    int off, int doPool, int doCount, int pingpong, int N) {
    __shared__ __half Bs[64][72];      // Wnext fp16
    __shared__ __half shA[16][72];     // h fp16 tile for ldmatrix
    __shared__ float sh[16][64];       // h fp32 for pooling
    __shared__ int sg[16];

    const __half* __restrict__ ysin = pingpong ? g_ysh2 : g_ysh;
    __half* __restrict__ ysout = pingpong ? g_ysh : g_ysh2;
    const uint2* __restrict__ ysv = (const uint2*)ysin;

    int tid = threadIdx.x;
    int node = blockIdx.x * 16 + (tid >> 4);
    int sl = tid & 15;
    bool valid = node < N;
    bool doGemm = (Wnext != nullptr);

    // stage Wnext (64x64 fp32 -> fp16), 16 halves per thread
    if (doGemm) {
        int row = tid >> 2;
        int cg = (tid & 3) * 16;
        const float4* p = (const float4*)(Wnext + row * 64 + cg);
        float4 f0 = p[0], f1 = p[1], f2 = p[2], f3 = p[3];
        uint4 u0, u1;
        u0.x = h2bits(__floats2half2_rn(f0.x, f0.y));
        u0.y = h2bits(__floats2half2_rn(f0.z, f0.w));
        u0.z = h2bits(__floats2half2_rn(f1.x, f1.y));
        u0.w = h2bits(__floats2half2_rn(f1.z, f1.w));
        u1.x = h2bits(__floats2half2_rn(f2.x, f2.y));
        u1.y = h2bits(__floats2half2_rn(f2.z, f2.w));
        u1.z = h2bits(__floats2half2_rn(f3.x, f3.y));
        u1.w = h2bits(__floats2half2_rn(f3.z, f3.w));
        *(uint4*)&Bs[row][cg] = u0;
        *(uint4*)&Bs[row][cg + 8] = u1;
    }

    // ---- aggregation (proven R13 loop, index prefetch) ----
    float h[4] = {0.f, 0.f, 0.f, 0.f};
    if (valid) {
        int beg = __ldg(&g_rowptr[node]);
        int end = __ldg(&g_rowptr[node + 1]);
        float dvn = __ldg(&g_dinv[node]);

        float s0[4] = {0.f, 0.f, 0.f, 0.f};
        float s1[4] = {0.f, 0.f, 0.f, 0.f};
        add_h4(s0, __ldg(&ysv[(size_t)node * 16 + sl]));  // self loop

        int e = beg;
        int c0 = 0, c1 = 0, c2 = 0, c3 = 0;
        bool have = (e + 4 <= end);
        if (have) {
            c0 = __ldg(&g_csr_src[e]);
            c1 = __ldg(&g_csr_src[e + 1]);
            c2 = __ldg(&g_csr_src[e + 2]);
            c3 = __ldg(&g_csr_src[e + 3]);
        }
        while (e + 8 <= end) {
            int m0 = __ldg(&g_csr_src[e + 4]);
            int m1 = __ldg(&g_csr_src[e + 5]);
            int m2 = __ldg(&g_csr_src[e + 6]);
            int m3 = __ldg(&g_csr_src[e + 7]);
            uint2 v0 = __ldg(&ysv[(size_t)c0 * 16 + sl]);
            uint2 v1 = __ldg(&ysv[(size_t)c1 * 16 + sl]);
            uint2 v2 = __ldg(&ysv[(size_t)c2 * 16 + sl]);
            uint2 v3 = __ldg(&ysv[(size_t)c3 * 16 + sl]);
            add_h4(s0, v0); add_h4(s1, v1);
            add_h4(s0, v2); add_h4(s1, v3);
            c0 = m0; c1 = m1; c2 = m2; c3 = m3;
            e += 4;
        }
        if (have) {
            uint2 v0 = __ldg(&ysv[(size_t)c0 * 16 + sl]);
            uint2 v1 = __ldg(&ysv[(size_t)c1 * 16 + sl]);
            uint2 v2 = __ldg(&ysv[(size_t)c2 * 16 + sl]);
            uint2 v3 = __ldg(&ysv[(size_t)c3 * 16 + sl]);
            add_h4(s0, v0); add_h4(s1, v1);
            add_h4(s0, v2); add_h4(s1, v3);
            e += 4;
        }
        for (; e < end; e++) {
            int a0 = __ldg(&g_csr_src[e]);
            add_h4(s0, __ldg(&ysv[(size_t)a0 * 16 + sl]));
        }

        float4 b4 = *(const float4*)(bias + sl * 4);
        float bb[4] = {b4.x, b4.y, b4.z, b4.w};
#pragma unroll
        for (int i = 0; i < 4; i++)
            h[i] = fmaxf((s0[i] + s1[i]) * dvn + bb[i], 0.f);
    }

    // stage h: fp16 tile for mma (always), fp32 tile for pooling
    {
        uint2 st;
        st.x = h2bits(__floats2half2_rn(h[0], h[1]));
        st.y = h2bits(__floats2half2_rn(h[2], h[3]));
        *(uint2*)&shA[tid >> 4][sl * 4] = st;
    }
    if (doPool) {
        *(float4*)&sh[tid >> 4][sl * 4] = make_float4(h[0], h[1], h[2], h[3]);
        if (sl == 0) sg[tid >> 4] = valid ? __ldg(&batch[node]) : -1;
    }
    __syncthreads();

    // ---- fused next-layer GEMM: 16x64 @ 64x64, 8 warps x 8-col strips ----
    if (doGemm) {
        int warp = tid >> 5;
        int lane = tid & 31;
        float acc0 = 0.f, acc1 = 0.f, acc2 = 0.f, acc3 = 0.f;
#pragma unroll
        for (int c = 0; c < 4; c++) {
            unsigned int a0, a1, a2, a3;
            unsigned int aaddr =
                smem_u32(&shA[lane & 15][c * 16 + (lane >> 4) * 8]);
            asm volatile(
                "ldmatrix.sync.aligned.m8n8.x4.shared.b16 {%0,%1,%2,%3}, [%4];"
                : "=r"(a0), "=r"(a1), "=r"(a2), "=r"(a3) : "r"(aaddr));
            unsigned int b0, b1, b2, b3;
            unsigned int baddr =
                smem_u32(&Bs[c * 16 + (lane & 15)][(warp >> 1) * 16 + (lane >> 4) * 8]);
            asm volatile(
                "ldmatrix.sync.aligned.m8n8.x4.trans.shared.b16 {%0,%1,%2,%3}, [%4];"
                : "=r"(b0), "=r"(b1), "=r"(b2), "=r"(b3) : "r"(baddr));
            unsigned int bb0 = (warp & 1) ? b2 : b0;
            unsigned int bb1 = (warp & 1) ? b3 : b1;
            asm volatile(
                "mma.sync.aligned.m16n8k16.row.col.f32.f16.f16.f32 "
                "{%0,%1,%2,%3}, {%4,%5,%6,%7}, {%8,%9}, {%0,%1,%2,%3};"
                : "+f"(acc0), "+f"(acc1), "+f"(acc2), "+f"(acc3)
                : "r"(a0), "r"(a1), "r"(a2), "r"(a3), "r"(bb0), "r"(bb1));
        }
        int r0 = lane >> 2;
        int n0 = blockIdx.x * 16 + r0;
        int n1 = n0 + 8;
        int col = warp * 8 + (lane & 3) * 2;
        if (n0 < N) {
            float dv = g_dinv[n0];
            __half2 p = __floats2half2_rn(acc0 * dv, acc1 * dv);
            *(__half2*)(ysout + (size_t)n0 * HID + col) = p;
        }
        if (n1 < N) {
            float dv = g_dinv[n1];
            __half2 p = __floats2half2_rn(acc2 * dv, acc3 * dv);
            *(__half2*)(ysout + (size_t)n1 * HID + col) = p;
        }
    }

    // ---- fused pooling ----
    if (doPool && tid < 64) {
        int gmin = 0x7fffffff, gmax = -1;
#pragma unroll
        for (int i = 0; i < 16; i++) {
            int g = sg[i];
            if (g >= 0) { gmin = min(gmin, g); gmax = max(gmax, g); }
        }
        for (int g = gmin; g <= gmax; g++) {
            float s = 0.f;
            int cnt = 0;
#pragma unroll
            for (int i = 0; i < 16; i++)
                if (sg[i] == g) { s += sh[i][tid]; cnt++; }
            atomicAdd(&g_pooled[g * JKDIM + off + tid], s);
            if (doCount && tid == 0) atomicAdd(&g_cnt[g], (float)cnt);
        }
    }
}

// ---------------- head: mean-pool normalize + linear + log_softmax ----------
__global__ void head_kernel(const float* __restrict__ Wl,
                            const float* __restrict__ bl,
                            float* __restrict__ out) {
    int g = threadIdx.x;
    if (g >= NGRAPHS) return;
    float ic = 1.f / fmaxf(g_cnt[g], 1.f);
    float logit[10];
#pragma unroll
    for (int j = 0; j < 10; j++) logit[j] = bl[j];
    for (int k = 0; k < JKDIM; k++) {
        float v = g_pooled[g * JKDIM + k] * ic;
#pragma unroll
        for (int j = 0; j < 10; j++) logit[j] += v * Wl[k * 10 + j];
    }
    float m = logit[0];
#pragma unroll
    for (int j = 1; j < 10; j++) m = fmaxf(m, logit[j]);
    float s = 0.f;
#pragma unroll
    for (int j = 0; j < 10; j++) s += expf(logit[j] - m);
    float lse = logf(s);
#pragma unroll
    for (int j = 0; j < 10; j++) out[g * 10 + j] = logit[j] - m - lse;
}

// ---------------- launch -----------------------------------------------------
extern "C" void kernel_launch(void* const* d_in, const int* in_sizes, int n_in,
                              void* d_out, int out_size) {
    const float* x  = (const float*)d_in[0];
    const float* W1 = (const float*)d_in[1];
    const float* b1 = (const float*)d_in[2];
    const float* W2 = (const float*)d_in[3];
    const float* b2 = (const float*)d_in[4];
    const float* W3 = (const float*)d_in[5];
    const float* b3 = (const float*)d_in[6];
    const float* W4 = (const float*)d_in[7];
    const float* b4 = (const float*)d_in[8];
    const float* Wl = (const float*)d_in[9];
    const float* bl = (const float*)d_in[10];
    const int* ei    = (const int*)d_in[11];
    const int* batch = (const int*)d_in[12];
    float* out = (float*)d_out;

    int N = in_sizes[12];
    int E = in_sizes[11] / 2;

    int threads = 256;
    int gridN = (N + threads - 1) / threads;
    int gridE = (E + threads - 1) / threads;
    int gemmGrid = (N + 127) / 128;
    int aggGrid = (N + 15) / 16;     // 16 nodes per block
    int nScanBlocks = (N + SCAN_BLK - 1) / SCAN_BLK;

    // one-time host-side stream/event resources (no device memory involved)
    static cudaStream_t s2 = nullptr;
    static cudaEvent_t evFork = nullptr, evJoin = nullptr;
    if (!s2) {
        cudaStreamCreateWithFlags(&s2, cudaStreamNonBlocking);
        cudaEventCreateWithFlags(&evFork, cudaEventDisableTiming);
        cudaEventCreateWithFlags(&evJoin, cudaEventDisableTiming);
    }

    zero_kernel<<<gridN, threads>>>(N);
    degree_kernel<<<gridE, threads>>>(ei, E);
    block_scan_kernel<<<nScanBlocks, SCAN_BLK>>>(N);   // dinv ready after this

    // fork: gemm1 (needs only x, W1, dinv) overlaps rest of CSR build
    cudaEventRecord(evFork, 0);
    cudaStreamWaitEvent(s2, evFork, 0);
    gemm_hmma<128><<<gemmGrid, 256, 0, s2>>>(x, W1, N);
    cudaEventRecord(evJoin, s2);

    scan_blocksums_kernel<<<1, MAX_SCAN_BLOCKS>>>(nScanBlocks);
    apply_offsets_kernel<<<gridN, threads>>>(N, E);
    fill_kernel<<<gridE, threads>>>(ei, E);

    cudaStreamWaitEvent(0, evJoin, 0);

    // layer 1: agg(ysh) + pool[0:64)+counts + fused gemm W2 -> ysh2
    agg_gemm_kernel<<<aggGrid, threads>>>(b1, batch, W2, 0, 1, 1, 0, N);
    // layer 2: agg(ysh2) + pool[64:128) + fused gemm W3 -> ysh
    agg_gemm_kernel<<<aggGrid, threads>>>(b2, batch, W3, 64, 1, 0, 1, N);
    // layer 3: agg(ysh) + fused gemm W4 -> ysh2 (no pool)
    agg_gemm_kernel<<<aggGrid, threads>>>(b3, batch, W4, 0, 0, 0, 0, N);
    // layer 4: agg(ysh2) + pool[128:192) (no gemm)
    agg_gemm_kernel<<<aggGrid, threads>>>(b4, batch, nullptr, 128, 1, 0, 1, N);

    head_kernel<<<1, 64>>>(Wl, bl, out);
}

// round 15
// speedup vs baseline: 1.0839x; 1.0839x over previous
#include <cuda_runtime.h>
#include <cuda_fp16.h>
#include <math.h>

#define NMAX 100000
#define EMAX 1600000
#define HID 64
#define NGRAPHS 64
#define JKDIM 192
#define SCAN_BLK 1024
#define MAX_SCAN_BLOCKS 128

// ---------------- scratch (device globals: no allocation allowed) ----------
__device__ int    g_deg[NMAX];
__device__ int    g_rowptr[NMAX + 1];
__device__ int    g_cursor[NMAX];
__device__ int    g_scanloc[NMAX];
__device__ int    g_blocksum[MAX_SCAN_BLOCKS];
__device__ int    g_blockoff[MAX_SCAN_BLOCKS];
__device__ int    g_csr_src[EMAX];
__device__ float  g_dinv[NMAX];
__device__ __half g_ysh[(size_t)NMAX * HID];  // dinv-scaled A@W, fp16
__device__ __half g_hh [(size_t)NMAX * HID];  // layer activations, fp16
__device__ float  g_pooled[NGRAPHS * JKDIM];
__device__ float  g_cnt[NGRAPHS];

__device__ __forceinline__ unsigned int h2bits(__half2 h) {
    return *(unsigned int*)&h;
}
__device__ __forceinline__ unsigned int smem_u32(const void* p) {
    unsigned int a;
    asm("{ .reg .u64 t; cvta.to.shared.u64 t, %1; cvt.u32.u64 %0, t; }"
        : "=r"(a) : "l"(p));
    return a;
}

// ---------------- init ------------------------------------------------------
__global__ void zero_kernel(int N) {
    int i = blockIdx.x * blockDim.x + threadIdx.x;
    if (i < N) g_deg[i] = 0;
    if (i < NGRAPHS * JKDIM) g_pooled[i] = 0.f;
    if (i < NGRAPHS) g_cnt[i] = 0.f;
}

__global__ void degree_kernel(const int* __restrict__ ei, int E) {
    int e = blockIdx.x * blockDim.x + threadIdx.x;
    if (e < E) atomicAdd(&g_deg[ei[E + e]], 1);
}

__global__ void dinv_kernel(int N) {
    int n = blockIdx.x * blockDim.x + threadIdx.x;
    if (n < N) g_dinv[n] = rsqrtf((float)(g_deg[n] + 1));  // +1 self loop
}

// ---------------- 3-phase grid-wide exclusive scan of g_deg -> g_rowptr -----
__global__ __launch_bounds__(SCAN_BLK) void block_scan_kernel(int N) {
    __shared__ int bs[SCAN_BLK];
    int t = threadIdx.x;
    int i = blockIdx.x * SCAN_BLK + t;
    int v = (i < N) ? g_deg[i] : 0;
    bs[t] = v;
    __syncthreads();
#pragma unroll
    for (int off = 1; off < SCAN_BLK; off <<= 1) {
        int u = (t >= off) ? bs[t - off] : 0;
        __syncthreads();
        bs[t] += u;
        __syncthreads();
    }
    if (i < N) g_scanloc[i] = bs[t] - v;
    if (t == SCAN_BLK - 1) g_blocksum[blockIdx.x] = bs[t];
}

__global__ void scan_blocksums_kernel(int nb) {
    __shared__ int bs[MAX_SCAN_BLOCKS];
    int t = threadIdx.x;
    int v = (t < nb) ? g_blocksum[t] : 0;
    bs[t] = v;
    __syncthreads();
#pragma unroll
    for (int off = 1; off < MAX_SCAN_BLOCKS; off <<= 1) {
        int u = (t >= off) ? bs[t - off] : 0;
        __syncthreads();
        bs[t] += u;
        __syncthreads();
    }
    if (t < nb) g_blockoff[t] = bs[t] - v;
}

__global__ void apply_offsets_kernel(int N, int E) {
    int i = blockIdx.x * blockDim.x + threadIdx.x;
    if (i < N) {
        int r = g_scanloc[i] + g_blockoff[i / SCAN_BLK];
        g_rowptr[i] = r;
        g_cursor[i] = r;
    }
    if (i == 0) g_rowptr[N] = E;
}

__global__ void fill_kernel(const int* __restrict__ ei, int E) {
    int e = blockIdx.x * blockDim.x + threadIdx.x;
    if (e < E) {
        int d = ei[E + e];
        int pos = atomicAdd(&g_cursor[d], 1);
        g_csr_src[pos] = ei[e];
    }
}

// -------- HMMA GEMM: ysh = fp16((A @ W) * dinv[row]) ------------------------
template <int KTOT, bool FP16IN>
__global__ __launch_bounds__(256) void gemm_hmma(const float* __restrict__ Af,
                                                 const float* __restrict__ W,
                                                 int N) {
    __shared__ __half As[128][40];
    __shared__ __half Bs[32][72];

    int tid = threadIdx.x;
    int warp = tid >> 5;
    int lane = tid & 31;
    int rowBase = blockIdx.x * 128;
    int wrow = warp * 16;

    float acc[8][4];
#pragma unroll
    for (int i = 0; i < 8; i++)
#pragma unroll
        for (int j = 0; j < 4; j++) acc[i][j] = 0.f;

    for (int kc = 0; kc < KTOT; kc += 32) {
        {
            int ar = tid >> 1;
            int ak = (tid & 1) * 16;
            int grow = rowBase + ar;
            uint4 u0 = make_uint4(0, 0, 0, 0);
            uint4 u1 = make_uint4(0, 0, 0, 0);
            if (FP16IN) {
                if (grow < N) {
                    const uint4* p = (const uint4*)(g_hh + (size_t)grow * KTOT + kc + ak);
                    u0 = p[0];
                    u1 = p[1];
                }
            } else {
                if (grow < N) {
                    const float4* p = (const float4*)(Af + (size_t)grow * KTOT + kc + ak);
                    float4 f0 = p[0], f1 = p[1], f2 = p[2], f3 = p[3];
                    u0.x = h2bits(__floats2half2_rn(f0.x, f0.y));
                    u0.y = h2bits(__floats2half2_rn(f0.z, f0.w));
                    u0.z = h2bits(__floats2half2_rn(f1.x, f1.y));
                    u0.w = h2bits(__floats2half2_rn(f1.z, f1.w));
                    u1.x = h2bits(__floats2half2_rn(f2.x, f2.y));
                    u1.y = h2bits(__floats2half2_rn(f2.z, f2.w));
                    u1.z = h2bits(__floats2half2_rn(f3.x, f3.y));
                    u1.w = h2bits(__floats2half2_rn(f3.z, f3.w));
                }
            }
            *(uint4*)&As[ar][ak] = u0;
            *(uint4*)&As[ar][ak + 8] = u1;
        }
        {
            int br = tid >> 3;
            int bc = (tid & 7) * 8;
            const float4* p = (const float4*)(W + (size_t)(kc + br) * 64 + bc);
            float4 w0 = p[0], w1 = p[1];
            uint4 u;
            u.x = h2bits(__floats2half2_rn(w0.x, w0.y));
            u.y = h2bits(__floats2half2_rn(w0.z, w0.w));
            u.z = h2bits(__floats2half2_rn(w1.x, w1.y));
            u.w = h2bits(__floats2half2_rn(w1.z, w1.w));
            *(uint4*)&Bs[br][bc] = u;
        }
        __syncthreads();

#pragma unroll
        for (int c = 0; c < 2; c++) {
            unsigned int a0, a1, a2, a3;
            unsigned int aaddr =
                smem_u32(&As[wrow + (lane & 15)][c * 16 + (lane >> 4) * 8]);
            asm volatile(
                "ldmatrix.sync.aligned.m8n8.x4.shared.b16 {%0,%1,%2,%3}, [%4];"
                : "=r"(a0), "=r"(a1), "=r"(a2), "=r"(a3) : "r"(aaddr));

#pragma unroll
            for (int nb = 0; nb < 8; nb += 2) {
                unsigned int b0, b1, b2, b3;
                unsigned int baddr =
                    smem_u32(&Bs[c * 16 + (lane & 15)][nb * 8 + (lane >> 4) * 8]);
                asm volatile(
                    "ldmatrix.sync.aligned.m8n8.x4.trans.shared.b16 {%0,%1,%2,%3}, [%4];"
                    : "=r"(b0), "=r"(b1), "=r"(b2), "=r"(b3) : "r"(baddr));
                asm volatile(
                    "mma.sync.aligned.m16n8k16.row.col.f32.f16.f16.f32 "
                    "{%0,%1,%2,%3}, {%4,%5,%6,%7}, {%8,%9}, {%0,%1,%2,%3};"
                    : "+f"(acc[nb][0]), "+f"(acc[nb][1]),
                      "+f"(acc[nb][2]), "+f"(acc[nb][3])
                    : "r"(a0), "r"(a1), "r"(a2), "r"(a3), "r"(b0), "r"(b1));
                asm volatile(
                    "mma.sync.aligned.m16n8k16.row.col.f32.f16.f16.f32 "
                    "{%0,%1,%2,%3}, {%4,%5,%6,%7}, {%8,%9}, {%0,%1,%2,%3};"
                    : "+f"(acc[nb + 1][0]), "+f"(acc[nb + 1][1]),
                      "+f"(acc[nb + 1][2]), "+f"(acc[nb + 1][3])
                    : "r"(a0), "r"(a1), "r"(a2), "r"(a3), "r"(b2), "r"(b3));
            }
        }
        __syncthreads();
    }

    int gID = lane >> 2;
    int tID = lane & 3;
    int r0 = rowBase + wrow + gID;
    int r1 = r0 + 8;
    float dv0 = (r0 < N) ? g_dinv[r0] : 0.f;
    float dv1 = (r1 < N) ? g_dinv[r1] : 0.f;
#pragma unroll
    for (int nb = 0; nb < 8; nb++) {
        int col = nb * 8 + tID * 2;
        if (r0 < N) {
            __half2 p = __floats2half2_rn(acc[nb][0] * dv0, acc[nb][1] * dv0);
            *(__half2*)(g_ysh + (size_t)r0 * HID + col) = p;
        }
        if (r1 < N) {
            __half2 p = __floats2half2_rn(acc[nb][2] * dv1, acc[nb][3] * dv1);
            *(__half2*)(g_ysh + (size_t)r1 * HID + col) = p;
        }
    }
}

// ---- aggregation: 16 thr/node, fp16 gather, pipelined index prefetch -------
// h[n] = relu(dinv[n]*(ysh[n] + sum ysh[src]) + b)
__device__ __forceinline__ void add_h4(float* acc, uint2 v) {
    __half2 h0 = *(__half2*)&v.x;
    __half2 h1 = *(__half2*)&v.y;
    float2 f0 = __half22float2(h0);
    float2 f1 = __half22float2(h1);
    acc[0] += f0.x; acc[1] += f0.y;
    acc[2] += f1.x; acc[3] += f1.y;
}

__global__ __launch_bounds__(256) void aggregate_kernel(
    const float* __restrict__ bias, const int* __restrict__ batch,
    int off, int doPool, int doCount, int writeH, int N) {
    int gid = blockIdx.x * blockDim.x + threadIdx.x;
    int node = gid >> 4;
    int sl = gid & 15;            // 4 halves (8 bytes) per thread
    bool valid = node < N;

    const uint2* __restrict__ ysv = (const uint2*)g_ysh;  // 16 uint2 per row

    float h[4] = {0.f, 0.f, 0.f, 0.f};

    if (valid) {
        int beg = __ldg(&g_rowptr[node]);
        int end = __ldg(&g_rowptr[node + 1]);
        float dvn = __ldg(&g_dinv[node]);

        float s0[4] = {0.f, 0.f, 0.f, 0.f};
        float s1[4] = {0.f, 0.f, 0.f, 0.f};
        add_h4(s0, __ldg(&ysv[(size_t)node * 16 + sl]));  // self loop

        int e = beg;
        int c0 = 0, c1 = 0, c2 = 0, c3 = 0;
        bool have = (e + 4 <= end);
        if (have) {
            c0 = __ldg(&g_csr_src[e]);
            c1 = __ldg(&g_csr_src[e + 1]);
            c2 = __ldg(&g_csr_src[e + 2]);
            c3 = __ldg(&g_csr_src[e + 3]);
        }
        while (e + 8 <= end) {
            // prefetch next quad's indices before consuming current gathers
            int m0 = __ldg(&g_csr_src[e + 4]);
            int m1 = __ldg(&g_csr_src[e + 5]);
            int m2 = __ldg(&g_csr_src[e + 6]);
            int m3 = __ldg(&g_csr_src[e + 7]);
            uint2 v0 = __ldg(&ysv[(size_t)c0 * 16 + sl]);
            uint2 v1 = __ldg(&ysv[(size_t)c1 * 16 + sl]);
            uint2 v2 = __ldg(&ysv[(size_t)c2 * 16 + sl]);
            uint2 v3 = __ldg(&ysv[(size_t)c3 * 16 + sl]);
            add_h4(s0, v0); add_h4(s1, v1);
            add_h4(s0, v2); add_h4(s1, v3);
            c0 = m0; c1 = m1; c2 = m2; c3 = m3;
            e += 4;
        }
        if (have) {
            uint2 v0 = __ldg(&ysv[(size_t)c0 * 16 + sl]);
            uint2 v1 = __ldg(&ysv[(size_t)c1 * 16 + sl]);
            uint2 v2 = __ldg(&ysv[(size_t)c2 * 16 + sl]);
            uint2 v3 = __ldg(&ysv[(size_t)c3 * 16 + sl]);
            add_h4(s0, v0); add_h4(s1, v1);
            add_h4(s0, v2); add_h4(s1, v3);
            e += 4;
        }
        for (; e < end; e++) {
            int a0 = __ldg(&g_csr_src[e]);
            add_h4(s0, __ldg(&ysv[(size_t)a0 * 16 + sl]));
        }

        float4 b4 = *(const float4*)(bias + sl * 4);
        float bb[4] = {b4.x, b4.y, b4.z, b4.w};
#pragma unroll
        for (int i = 0; i < 4; i++)
            h[i] = fmaxf((s0[i] + s1[i]) * dvn + bb[i], 0.f);

        if (writeH) {
            uint2 st;
            st.x = h2bits(__floats2half2_rn(h[0], h[1]));
            st.y = h2bits(__floats2half2_rn(h[2], h[3]));
            *(uint2*)(g_hh + (size_t)node * HID + sl * 4) = st;
        }
    }

    if (doPool) {
        __shared__ float sh[16][64];
        __shared__ int sg[16];
        int nl = threadIdx.x >> 4;
        int sli = threadIdx.x & 15;
        *(float4*)&sh[nl][sli * 4] = make_float4(h[0], h[1], h[2], h[3]);
        if (sli == 0) sg[nl] = valid ? __ldg(&batch[node]) : -1;
        __syncthreads();

        if (threadIdx.x < 64) {
            int gmin = 0x7fffffff, gmax = -1;
#pragma unroll
            for (int i = 0; i < 16; i++) {
                int g = sg[i];
                if (g >= 0) { gmin = min(gmin, g); gmax = max(gmax, g); }
            }
            for (int g = gmin; g <= gmax; g++) {
                float s = 0.f;
                int cnt = 0;
#pragma unroll
                for (int i = 0; i < 16; i++)
                    if (sg[i] == g) { s += sh[i][threadIdx.x]; cnt++; }
                atomicAdd(&g_pooled[g * JKDIM + off + threadIdx.x], s);
                if (doCount && threadIdx.x == 0) atomicAdd(&g_cnt[g], (float)cnt);
            }
        }
    }
}

// ---------------- head: mean-pool normalize + linear + log_softmax ----------
__global__ void head_kernel(const float* __restrict__ Wl,
                            const float* __restrict__ bl,
                            float* __restrict__ out) {
    int g = threadIdx.x;
    if (g >= NGRAPHS) return;
    float ic = 1.f / fmaxf(g_cnt[g], 1.f);
    float logit[10];
#pragma unroll
    for (int j = 0; j < 10; j++) logit[j] = bl[j];
    for (int k = 0; k < JKDIM; k++) {
        float v = g_pooled[g * JKDIM + k] * ic;
#pragma unroll
        for (int j = 0; j < 10; j++) logit[j] += v * Wl[k * 10 + j];
    }
    float m = logit[0];
#pragma unroll
    for (int j = 1; j < 10; j++) m = fmaxf(m, logit[j]);
    float s = 0.f;
#pragma unroll
    for (int j = 0; j < 10; j++) s += expf(logit[j] - m);
    float lse = logf(s);
#pragma unroll
    for (int j = 0; j < 10; j++) out[g * 10 + j] = logit[j] - m - lse;
}

// ---------------- launch -----------------------------------------------------
extern "C" void kernel_launch(void* const* d_in, const int* in_sizes, int n_in,
                              void* d_out, int out_size) {
    const float* x  = (const float*)d_in[0];
    const float* W1 = (const float*)d_in[1];
    const float* b1 = (const float*)d_in[2];
    const float* W2 = (const float*)d_in[3];
    const float* b2 = (const float*)d_in[4];
    const float* W3 = (const float*)d_in[5];
    const float* b3 = (const float*)d_in[6];
    const float* W4 = (const float*)d_in[7];
    const float* b4 = (const float*)d_in[8];
    const float* Wl = (const float*)d_in[9];
    const float* bl = (const float*)d_in[10];
    const int* ei    = (const int*)d_in[11];
    const int* batch = (const int*)d_in[12];
    float* out = (float*)d_out;

    int N = in_sizes[12];
    int E = in_sizes[11] / 2;

    int threads = 256;
    int gridN = (N + threads - 1) / threads;
    int gridE = (E + threads - 1) / threads;
    int gemmGrid = (N + 127) / 128;
    int aggGrid = (N * 16 + threads - 1) / threads;
    int nScanBlocks = (N + SCAN_BLK - 1) / SCAN_BLK;

    // one-time host-side stream/event resources (no device memory involved)
    static cudaStream_t s2 = nullptr;
    static cudaEvent_t evFork = nullptr, evJoin = nullptr;
    if (!s2) {
        cudaStreamCreateWithFlags(&s2, cudaStreamNonBlocking);
        cudaEventCreateWithFlags(&evFork, cudaEventDisableTiming);
        cudaEventCreateWithFlags(&evJoin, cudaEventDisableTiming);
    }

    zero_kernel<<<gridN, threads>>>(N);
    degree_kernel<<<gridE, threads>>>(ei, E);
    dinv_kernel<<<gridN, threads>>>(N);   // dinv ready — fork point

    // fork: gemm1 (needs only x, W1, dinv) overlaps the whole scan+fill chain
    cudaEventRecord(evFork, 0);
    cudaStreamWaitEvent(s2, evFork, 0);
    gemm_hmma<128, false><<<gemmGrid, 256, 0, s2>>>(x, W1, N);
    cudaEventRecord(evJoin, s2);

    block_scan_kernel<<<nScanBlocks, SCAN_BLK>>>(N);
    scan_blocksums_kernel<<<1, MAX_SCAN_BLOCKS>>>(nScanBlocks);
    apply_offsets_kernel<<<gridN, threads>>>(N, E);
    fill_kernel<<<gridE, threads>>>(ei, E);

    cudaStreamWaitEvent(0, evJoin, 0);

    // layer 1; pool x1 -> [0:64), counts
    aggregate_kernel<<<aggGrid, threads>>>(b1, batch, 0, 1, 1, 1, N);

    // layer 2; pool x2 -> [64:128)
    gemm_hmma<64, true><<<gemmGrid, 256>>>(nullptr, W2, N);
    aggregate_kernel<<<aggGrid, threads>>>(b2, batch, 64, 1, 0, 1, N);

    // layer 3 (no pool)
    gemm_hmma<64, true><<<gemmGrid, 256>>>(nullptr, W3, N);
    aggregate_kernel<<<aggGrid, threads>>>(b3, batch, 0, 0, 0, 1, N);

    // layer 4 (overwrites x3); pool -> [128:192); h never read again
    gemm_hmma<64, true><<<gemmGrid, 256>>>(nullptr, W4, N);
    aggregate_kernel<<<aggGrid, threads>>>(b4, batch, 128, 1, 0, 0, N);

    head_kernel<<<1, 64>>>(Wl, bl, out);
}